// round 14
// baseline (speedup 1.0000x reference)
#include <cuda_runtime.h>
#include <cuda_fp16.h>
#include <cstdint>

// Problem constants
#define NN 100000           // nodes
#define NR 4                // relations
#define NE 500000           // edges per relation
#define DD 128              // feature dim (in == out)
#define PAD 32              // max edges per (relation, dst) bucket in padded CSR
#define OVF_CAP 2048        // fallback list capacity for bucket overflow

// Scratch (device globals: allocation-free rule)
__device__ __half2 g_zh[(size_t)NR * NN * (DD / 2)];  // z in fp16 (~102MB)
__device__ int g_cnt[NR * NN];                 // per-(r,dst) edge counts (== degree)
__device__ int g_slot[(size_t)NR * NN * PAD];  // padded CSR: src indices
__device__ int g_ovf[OVF_CAP];                 // overflow edge ids (r*NE+e)
__device__ int g_ovf_n;

// ---------------------------------------------------------------------------
// f32x2 packed helpers (base sm_10x ISA)
__device__ __forceinline__ uint64_t pack2(float lo, float hi) {
    uint64_t d;
    asm("mov.b64 %0, {%1, %2};" : "=l"(d) : "f"(lo), "f"(hi));
    return d;
}
__device__ __forceinline__ uint64_t pack_rep(float v) {
    uint64_t d;
    asm("mov.b64 %0, {%1, %1};" : "=l"(d) : "f"(v));
    return d;
}
__device__ __forceinline__ void unpack2(float& lo, float& hi, uint64_t v) {
    asm("mov.b64 {%0, %1}, %2;" : "=f"(lo), "=f"(hi) : "l"(v));
}
__device__ __forceinline__ void ffma2(uint64_t& d, uint64_t a, uint64_t b) {
    asm("fma.rn.f32x2 %0, %1, %2, %3;" : "=l"(d) : "l"(a), "l"(b), "l"(d));
}

// ---------------------------------------------------------------------------
__global__ void k_zero_cnt() {
    int i = blockIdx.x * blockDim.x + threadIdx.x;
    if (i < NR * NN) g_cnt[i] = 0;
    if (i == 0) g_ovf_n = 0;
}

// Build padded bucket-CSR: slot[r][dst][c] = src. Overflow -> fallback list.
__global__ void k_fill(const int* __restrict__ src_idx,
                       const int* __restrict__ dst_idx) {
    int i = blockIdx.x * blockDim.x + threadIdx.x;
    if (i >= NR * NE) return;
    int r = i / NE;
    int dst = dst_idx[i];
    int c = atomicAdd(&g_cnt[r * NN + dst], 1);
    if (c < PAD) {
        g_slot[((size_t)r * NN + dst) * PAD + c] = src_idx[i];
    } else {
        int o = atomicAdd(&g_ovf_n, 1);
        if (o < OVF_CAP) g_ovf[o] = i;
    }
}

// ---------------------------------------------------------------------------
// GEMM: for r in 0..3: z[r][m0:m0+64] = x_tile @ W[r], z stored fp16.
#define BM 64
#define AS_STRIDE 33
#define AS_BYTES (DD * AS_STRIDE * 8)        // 33792
#define SMEM_TOTAL (AS_BYTES + DD * DD * 4)  // 99328

__global__ __launch_bounds__(256) void k_gemm3(const float* __restrict__ x,
                                               const float* __restrict__ W) {
    extern __shared__ char smem[];
    uint64_t* As2 = (uint64_t*)smem;
    float* Bs = (float*)(smem + AS_BYTES);

    const int tid = threadIdx.x;
    const int wid = tid >> 5, lane = tid & 31;
    const int m0 = blockIdx.x * BM;

#pragma unroll
    for (int pass = 0; pass < 4; pass++) {
        int idx = pass * 256 + tid;
        int p = idx >> 5;
        int k4 = idx & 31;
        int r0 = m0 + 2 * p;
        float4 v0 = make_float4(0.f, 0.f, 0.f, 0.f), v1 = v0;
        if (r0 < NN)     v0 = ((const float4*)(x + (size_t)r0 * DD))[k4];
        if (r0 + 1 < NN) v1 = ((const float4*)(x + (size_t)(r0 + 1) * DD))[k4];
        As2[(k4 * 4 + 0) * AS_STRIDE + p] = pack2(v0.x, v1.x);
        As2[(k4 * 4 + 1) * AS_STRIDE + p] = pack2(v0.y, v1.y);
        As2[(k4 * 4 + 2) * AS_STRIDE + p] = pack2(v0.z, v1.z);
        As2[(k4 * 4 + 3) * AS_STRIDE + p] = pack2(v0.w, v1.w);
    }

    for (int r = 0; r < NR; r++) {
        {
            const float4* Wv = (const float4*)(W + (size_t)r * DD * DD);
            float4* Bv = (float4*)Bs;
#pragma unroll
            for (int i = 0; i < 16; i++) Bv[i * 256 + tid] = Wv[i * 256 + tid];
        }
        __syncthreads();

        uint64_t acc[4][4];
#pragma unroll
        for (int i = 0; i < 4; i++)
#pragma unroll
            for (int j = 0; j < 4; j++) acc[i][j] = 0ull;

        const uint64_t* arow = As2 + wid * 4;
        const float4* brow = (const float4*)Bs + lane;

#pragma unroll 16
        for (int k = 0; k < DD; k++) {
            uint64_t a0 = arow[k * AS_STRIDE + 0];
            uint64_t a1 = arow[k * AS_STRIDE + 1];
            uint64_t a2 = arow[k * AS_STRIDE + 2];
            uint64_t a3 = arow[k * AS_STRIDE + 3];
            float4 bv = brow[k * 32];
            uint64_t b0 = pack_rep(bv.x), b1 = pack_rep(bv.y);
            uint64_t b2 = pack_rep(bv.z), b3 = pack_rep(bv.w);
            ffma2(acc[0][0], a0, b0); ffma2(acc[0][1], a0, b1);
            ffma2(acc[0][2], a0, b2); ffma2(acc[0][3], a0, b3);
            ffma2(acc[1][0], a1, b0); ffma2(acc[1][1], a1, b1);
            ffma2(acc[1][2], a1, b2); ffma2(acc[1][3], a1, b3);
            ffma2(acc[2][0], a2, b0); ffma2(acc[2][1], a2, b1);
            ffma2(acc[2][2], a2, b2); ffma2(acc[2][3], a2, b3);
            ffma2(acc[3][0], a3, b0); ffma2(acc[3][1], a3, b1);
            ffma2(acc[3][2], a3, b2); ffma2(acc[3][3], a3, b3);
        }
        __syncthreads();

        uint2* zr = (uint2*)(g_zh + ((size_t)r * NN) * (DD / 2));
#pragma unroll
        for (int ip = 0; ip < 4; ip++) {
            int re = m0 + wid * 8 + ip * 2;
            float4 lo, hi;
            unpack2(lo.x, hi.x, acc[ip][0]);
            unpack2(lo.y, hi.y, acc[ip][1]);
            unpack2(lo.z, hi.z, acc[ip][2]);
            unpack2(lo.w, hi.w, acc[ip][3]);
            if (re < NN) {
                __half2 h01 = __floats2half2_rn(lo.x, lo.y);
                __half2 h23 = __floats2half2_rn(lo.z, lo.w);
                uint2 u; u.x = *(uint32_t*)&h01; u.y = *(uint32_t*)&h23;
                zr[(size_t)re * 32 + lane] = u;
            }
            if (re + 1 < NN) {
                __half2 h01 = __floats2half2_rn(hi.x, hi.y);
                __half2 h23 = __floats2half2_rn(hi.z, hi.w);
                uint2 u; u.x = *(uint32_t*)&h01; u.y = *(uint32_t*)&h23;
                zr[(size_t)(re + 1) * 32 + lane] = u;
            }
        }
    }
}

// ---------------------------------------------------------------------------
// Gather + bias + ReLU, fused. One warp per dst node.
// Per relation: ONE coalesced LDG loads the 32-slot bucket (lane j -> sl[j]);
// srcs broadcast via shfl; gathers unrolled x4 for MLP. fp32 accumulate,
// scale by 1/deg, sum relations, add bias, ReLU, single STG per row.
__device__ __forceinline__ void h2acc(float4& acc, uint2 u) {
    float2 f01 = __half22float2(*(__half2*)&u.x);
    float2 f23 = __half22float2(*(__half2*)&u.y);
    acc.x += f01.x; acc.y += f01.y; acc.z += f23.x; acc.w += f23.y;
}

__global__ __launch_bounds__(256) void k_scatter3(const int* __restrict__ src_idx,
                                                  const int* __restrict__ dst_idx,
                                                  const float* __restrict__ b,
                                                  float* __restrict__ out) {
    int gw = blockIdx.x * (blockDim.x >> 5) + (threadIdx.x >> 5);   // dst node
    int lane = threadIdx.x & 31;
    if (gw >= NN) return;

    // Per-lane bias sums for cols lane*4 .. lane*4+3
    float4 bsum;
    {
        int c = lane * 4;
        bsum.x = b[c + 0] + b[DD + c + 0] + b[2 * DD + c + 0] + b[3 * DD + c + 0];
        bsum.y = b[c + 1] + b[DD + c + 1] + b[2 * DD + c + 1] + b[3 * DD + c + 1];
        bsum.z = b[c + 2] + b[DD + c + 2] + b[2 * DD + c + 2] + b[3 * DD + c + 2];
        bsum.w = b[c + 3] + b[DD + c + 3] + b[2 * DD + c + 3] + b[3 * DD + c + 3];
    }
    const int ovfn = min(g_ovf_n, OVF_CAP);   // normally 0

    float4 tot = make_float4(bsum.x, bsum.y, bsum.z, bsum.w);
#pragma unroll
    for (int r = 0; r < NR; r++) {
        int cnt = g_cnt[r * NN + gw];                 // warp-uniform
        int n = min(cnt, PAD);
        const int* sl = g_slot + ((size_t)r * NN + gw) * PAD;
        // ONE coalesced 128B load fetches the whole bucket
        int myidx = (lane < n) ? sl[lane] : 0;
        const uint2* zr = (const uint2*)(g_zh + ((size_t)r * NN) * (DD / 2));

        float4 acc = make_float4(0.f, 0.f, 0.f, 0.f);
        int j = 0;
        for (; j + 4 <= n; j += 4) {                  // 4 gathers in flight
            int s0 = __shfl_sync(0xffffffffu, myidx, j + 0);
            int s1 = __shfl_sync(0xffffffffu, myidx, j + 1);
            int s2 = __shfl_sync(0xffffffffu, myidx, j + 2);
            int s3 = __shfl_sync(0xffffffffu, myidx, j + 3);
            uint2 u0 = zr[(size_t)s0 * 32 + lane];
            uint2 u1 = zr[(size_t)s1 * 32 + lane];
            uint2 u2 = zr[(size_t)s2 * 32 + lane];
            uint2 u3 = zr[(size_t)s3 * 32 + lane];
            h2acc(acc, u0); h2acc(acc, u1); h2acc(acc, u2); h2acc(acc, u3);
        }
        for (; j < n; j++) {
            int s = __shfl_sync(0xffffffffu, myidx, j);
            uint2 u = zr[(size_t)s * 32 + lane];
            h2acc(acc, u);
        }
        if (ovfn > 0) {                               // rare bucket overflow
            for (int k = 0; k < ovfn; k++) {
                int i = g_ovf[k];
                if (i / NE == r && dst_idx[i] == gw) {
                    uint2 u = zr[(size_t)src_idx[i] * 32 + lane];
                    h2acc(acc, u);
                }
            }
        }
        float inv = 1.0f / (float)max(cnt, 1);
        tot.x += acc.x * inv; tot.y += acc.y * inv;
        tot.z += acc.z * inv; tot.w += acc.w * inv;
    }
    // ReLU + store
    tot.x = fmaxf(tot.x, 0.f); tot.y = fmaxf(tot.y, 0.f);
    tot.z = fmaxf(tot.z, 0.f); tot.w = fmaxf(tot.w, 0.f);
    ((float4*)(out + (size_t)gw * DD))[lane] = tot;
}

// ---------------------------------------------------------------------------
extern "C" void kernel_launch(void* const* d_in, const int* in_sizes, int n_in,
                              void* d_out, int out_size) {
    const float* x = (const float*)d_in[0];      // [100000,128]
    const float* W = (const float*)d_in[1];      // [4,128,128]
    const float* b = (const float*)d_in[2];      // [4,128]
    const int* src_idx = (const int*)d_in[3];    // [4,500000]
    const int* dst_idx = (const int*)d_in[4];    // [4,500000]
    float* out = (float*)d_out;                  // [100000,128]

    cudaFuncSetAttribute(k_gemm3, cudaFuncAttributeMaxDynamicSharedMemorySize,
                         SMEM_TOTAL);

    // Build padded bucket-CSR (counts double as degrees).
    k_zero_cnt<<<(NR * NN + 255) / 256, 256>>>();
    k_fill<<<(NR * NE + 255) / 256, 256>>>(src_idx, dst_idx);

    // z[r] = x @ W[r] (fp16 store), all relations per block
    int mtiles = (NN + BM - 1) / BM;             // 1563
    k_gemm3<<<mtiles, 256, SMEM_TOTAL>>>(x, W);

    // Fused gather + bias + ReLU (handles overflow inline; writes every row).
    k_scatter3<<<(NN + 7) / 8, 256>>>(src_idx, dst_idx, b, out);
}

// round 15
// speedup vs baseline: 2.0331x; 2.0331x over previous
#include <cuda_runtime.h>
#include <cuda_fp16.h>
#include <cstdint>

// Problem constants
#define NN 100000           // nodes
#define NR 4                // relations
#define NE 500000           // edges per relation
#define DD 128              // feature dim (in == out)
#define PAD 32              // max edges per (relation, dst) bucket in padded CSR
#define OVF_CAP 2048        // fallback list capacity for bucket overflow

// Scratch (device globals: allocation-free rule)
__device__ __half2 g_zh[(size_t)NR * NN * (DD / 2)];  // z in fp16 (~102MB)
__device__ int g_cnt[NR * NN];                 // per-(r,dst) edge counts (== degree)
__device__ int g_slot[(size_t)NR * NN * PAD];  // padded CSR: src indices
__device__ int g_ovf[OVF_CAP];                 // overflow edge ids (r*NE+e)
__device__ int g_ovf_n;

// ---------------------------------------------------------------------------
__device__ __forceinline__ uint32_t smem_u32(const void* p) {
    uint32_t a;
    asm("{ .reg .u64 t; cvta.to.shared.u64 t, %1; cvt.u32.u64 %0, t; }"
        : "=r"(a) : "l"(p));
    return a;
}
__device__ __forceinline__ void ldsm4(uint32_t* d, uint32_t addr) {
    asm volatile("ldmatrix.sync.aligned.m8n8.x4.shared.b16 {%0,%1,%2,%3}, [%4];"
                 : "=r"(d[0]), "=r"(d[1]), "=r"(d[2]), "=r"(d[3]) : "r"(addr));
}
__device__ __forceinline__ void ldsm2t(uint32_t* d, uint32_t addr) {
    asm volatile("ldmatrix.sync.aligned.m8n8.x2.trans.shared.b16 {%0,%1}, [%2];"
                 : "=r"(d[0]), "=r"(d[1]) : "r"(addr));
}
__device__ __forceinline__ void mma16816(float* d, const uint32_t* a,
                                         const uint32_t* b) {
    asm volatile(
        "mma.sync.aligned.m16n8k16.row.col.f32.f16.f16.f32 "
        "{%0,%1,%2,%3}, {%4,%5,%6,%7}, {%8,%9}, {%0,%1,%2,%3};"
        : "+f"(d[0]), "+f"(d[1]), "+f"(d[2]), "+f"(d[3])
        : "r"(a[0]), "r"(a[1]), "r"(a[2]), "r"(a[3]), "r"(b[0]), "r"(b[1]));
}

// ---------------------------------------------------------------------------
__global__ void k_zero_cnt() {
    int i = blockIdx.x * blockDim.x + threadIdx.x;
    if (i < NR * NN) g_cnt[i] = 0;
    if (i == 0) g_ovf_n = 0;
}

__global__ void k_fill(const int* __restrict__ src_idx,
                       const int* __restrict__ dst_idx) {
    int i = blockIdx.x * blockDim.x + threadIdx.x;
    if (i >= NR * NE) return;
    int r = i / NE;
    int dst = dst_idx[i];
    int c = atomicAdd(&g_cnt[r * NN + dst], 1);
    if (c < PAD) {
        g_slot[((size_t)r * NN + dst) * PAD + c] = src_idx[i];
    } else {
        int o = atomicAdd(&g_ovf_n, 1);
        if (o < OVF_CAP) g_ovf[o] = i;
    }
}

// ---------------------------------------------------------------------------
// HMMA GEMM: per block, 128 rows x 128 cols, K=128, all 4 relations.
// Split fp16: z = xh*Wh + xl*Wh + xh*Wl (fp32 accum), stored fp16.
// A: [m][k] fp16 (row-major, direct convert). B: [k][n] fp16 (direct convert),
// loaded with ldmatrix.x2.trans for the col-major B operand of mma row.col.
#define LDS_H 136                              // halfs per smem row (128 + 8 pad)
#define TILE_BYTES (128 * LDS_H * 2)           // 34816
#define SM_AH 0
#define SM_AL TILE_BYTES
#define SM_BH (2 * TILE_BYTES)
#define SM_BL (3 * TILE_BYTES)
#define SMEM_MMA (4 * TILE_BYTES)              // 139264

__global__ __launch_bounds__(256) void k_gemm_mma(const float* __restrict__ x,
                                                  const float* __restrict__ W) {
    extern __shared__ char smem[];
    __half* Ah = (__half*)(smem + SM_AH);
    __half* Al = (__half*)(smem + SM_AL);
    __half* Bh = (__half*)(smem + SM_BH);
    __half* Bl = (__half*)(smem + SM_BL);

    const int tid = threadIdx.x;
    const int lane = tid & 31, wid = tid >> 5;
    const int warp_m = wid >> 1, warp_n = wid & 1;   // 4 x 2 warp grid
    const int m0 = blockIdx.x * 128;

    // ---- Convert x tile -> Ah/Al ([m][k], row-major, coalesced)
#pragma unroll
    for (int it = 0; it < 16; it++) {
        int idx = it * 256 + tid;            // 4096 float4s = 128 rows x 32
        int row = idx >> 5;
        int c = (idx & 31) * 4;
        float4 v = make_float4(0.f, 0.f, 0.f, 0.f);
        if (m0 + row < NN) v = ((const float4*)(x + (size_t)(m0 + row) * DD))[idx & 31];
        __half hx = __float2half_rn(v.x), hy = __float2half_rn(v.y);
        __half hz = __float2half_rn(v.z), hw = __float2half_rn(v.w);
        __half lx = __float2half_rn(v.x - __half2float(hx));
        __half ly = __float2half_rn(v.y - __half2float(hy));
        __half lz = __float2half_rn(v.z - __half2float(hz));
        __half lw = __float2half_rn(v.w - __half2float(hw));
        int off = row * LDS_H + c;
        *(__half2*)(Ah + off)     = __halves2half2(hx, hy);
        *(__half2*)(Ah + off + 2) = __halves2half2(hz, hw);
        *(__half2*)(Al + off)     = __halves2half2(lx, ly);
        *(__half2*)(Al + off + 2) = __halves2half2(lz, lw);
    }

    const uint32_t ah_b = smem_u32(Ah), al_b = smem_u32(Al);
    const uint32_t bh_b = smem_u32(Bh), bl_b = smem_u32(Bl);
    // A ldmatrix addr: lanes 0-7 -> rows m+0..7 @k0; 8-15 -> m+8..15 @k0;
    // 16-23 -> m+0..7 @k8; 24-31 -> m+8..15 @k8  (matches a0..a3 frag order)
    const uint32_t aoff0 = ((warp_m * 32 + (lane & 7) + ((lane >> 3) & 1) * 8) * LDS_H
                            + ((lane >> 4) & 1) * 8) * 2;
    // B ldmatrix.trans addr: lanes 0-15 -> rows k0+0..15, col n0
    const uint32_t boff0 = ((lane & 15) * LDS_H + warp_n * 64) * 2;

    float acc[2][8][4];

    for (int r = 0; r < NR; r++) {
        __syncthreads();   // prior relation's mma done before B overwrite

        // ---- Convert W_r -> Bh/Bl ([k][n], row-major, coalesced)
#pragma unroll
        for (int it = 0; it < 16; it++) {
            int idx = it * 256 + tid;
            int k = idx >> 5;
            int n = (idx & 31) * 4;
            float4 v = ((const float4*)(W + (size_t)r * DD * DD + (size_t)k * DD))[idx & 31];
            __half hx = __float2half_rn(v.x), hy = __float2half_rn(v.y);
            __half hz = __float2half_rn(v.z), hw = __float2half_rn(v.w);
            __half lx = __float2half_rn(v.x - __half2float(hx));
            __half ly = __float2half_rn(v.y - __half2float(hy));
            __half lz = __float2half_rn(v.z - __half2float(hz));
            __half lw = __float2half_rn(v.w - __half2float(hw));
            int off = k * LDS_H + n;
            *(__half2*)(Bh + off)     = __halves2half2(hx, hy);
            *(__half2*)(Bh + off + 2) = __halves2half2(hz, hw);
            *(__half2*)(Bl + off)     = __halves2half2(lx, ly);
            *(__half2*)(Bl + off + 2) = __halves2half2(lz, lw);
        }
        __syncthreads();

#pragma unroll
        for (int i = 0; i < 2; i++)
#pragma unroll
            for (int j = 0; j < 8; j++)
#pragma unroll
                for (int q = 0; q < 4; q++) acc[i][j][q] = 0.f;

        for (int ks = 0; ks < 8; ks++) {
            uint32_t ah0[4], ah1[4], al0[4], al1[4];
            uint32_t kadd = (uint32_t)ks * 32;       // ks*16 halfs = 32B
            ldsm4(ah0, ah_b + aoff0 + kadd);
            ldsm4(ah1, ah_b + aoff0 + 16 * LDS_H * 2 + kadd);
            ldsm4(al0, al_b + aoff0 + kadd);
            ldsm4(al1, al_b + aoff0 + 16 * LDS_H * 2 + kadd);
            uint32_t krow = (uint32_t)ks * 16 * LDS_H * 2;   // B k-offset
#pragma unroll
            for (int nf = 0; nf < 8; nf++) {
                uint32_t bh[2], bl[2];
                uint32_t boff = boff0 + krow + nf * 16;      // nf*8 halfs
                ldsm2t(bh, bh_b + boff);
                ldsm2t(bl, bl_b + boff);
                mma16816(acc[0][nf], ah0, bh);
                mma16816(acc[1][nf], ah1, bh);
                mma16816(acc[0][nf], al0, bh);
                mma16816(acc[1][nf], al1, bh);
                mma16816(acc[0][nf], ah0, bl);
                mma16816(acc[1][nf], ah1, bl);
            }
        }

        // ---- Epilogue: d frag (row lane/4 [+8], col 2*(lane%4)+{0,1}) -> fp16 z
        uint32_t* zb = (uint32_t*)(g_zh + (size_t)r * NN * (DD / 2));
        int r0 = m0 + warp_m * 32 + (lane >> 2);
        int cb = warp_n * 64 + 2 * (lane & 3);
#pragma unroll
        for (int mt = 0; mt < 2; mt++) {
#pragma unroll
            for (int nf = 0; nf < 8; nf++) {
                int row1 = r0 + mt * 16;
                int row2 = row1 + 8;
                int col = cb + nf * 8;
                __half2 p1 = __floats2half2_rn(acc[mt][nf][0], acc[mt][nf][1]);
                __half2 p2 = __floats2half2_rn(acc[mt][nf][2], acc[mt][nf][3]);
                if (row1 < NN) zb[row1 * 64 + (col >> 1)] = *(uint32_t*)&p1;
                if (row2 < NN) zb[row2 * 64 + (col >> 1)] = *(uint32_t*)&p2;
            }
        }
    }
}

// ---------------------------------------------------------------------------
// Gather + bias + ReLU fused (R12-proven serial gather; compiler interleaves
// the 4 unrolled relation chains for MLP). One warp per dst node.
__global__ __launch_bounds__(256) void k_scatter_f(const int* __restrict__ src_idx,
                                                   const int* __restrict__ dst_idx,
                                                   const float* __restrict__ b,
                                                   float* __restrict__ out) {
    int gw = blockIdx.x * (blockDim.x >> 5) + (threadIdx.x >> 5);   // dst node
    int lane = threadIdx.x & 31;
    if (gw >= NN) return;

    float4 tot;
    {
        int c = lane * 4;
        tot.x = b[c + 0] + b[DD + c + 0] + b[2 * DD + c + 0] + b[3 * DD + c + 0];
        tot.y = b[c + 1] + b[DD + c + 1] + b[2 * DD + c + 1] + b[3 * DD + c + 1];
        tot.z = b[c + 2] + b[DD + c + 2] + b[2 * DD + c + 2] + b[3 * DD + c + 2];
        tot.w = b[c + 3] + b[DD + c + 3] + b[2 * DD + c + 3] + b[3 * DD + c + 3];
    }
    const int ovfn = min(g_ovf_n, OVF_CAP);   // normally 0

#pragma unroll
    for (int r = 0; r < NR; r++) {
        int cnt = g_cnt[r * NN + gw];                 // warp-uniform broadcast
        int n = min(cnt, PAD);
        const int* sl = g_slot + ((size_t)r * NN + gw) * PAD;
        const uint2* zr = (const uint2*)(g_zh + ((size_t)r * NN) * (DD / 2));
        float4 acc = make_float4(0.f, 0.f, 0.f, 0.f);
        for (int j = 0; j < n; j++) {
            int src = sl[j];                          // warp-uniform broadcast
            uint2 u = zr[(size_t)src * 32 + lane];    // 8B/lane (4 fp16 cols)
            float2 f01 = __half22float2(*(__half2*)&u.x);
            float2 f23 = __half22float2(*(__half2*)&u.y);
            acc.x += f01.x; acc.y += f01.y; acc.z += f23.x; acc.w += f23.y;
        }
        if (ovfn > 0) {                               // rare bucket overflow
            for (int k = 0; k < ovfn; k++) {
                int i = g_ovf[k];
                if (i / NE == r && dst_idx[i] == gw) {
                    uint2 u = zr[(size_t)src_idx[i] * 32 + lane];
                    float2 f01 = __half22float2(*(__half2*)&u.x);
                    float2 f23 = __half22float2(*(__half2*)&u.y);
                    acc.x += f01.x; acc.y += f01.y; acc.z += f23.x; acc.w += f23.y;
                }
            }
        }
        float inv = 1.0f / (float)max(cnt, 1);
        tot.x += acc.x * inv; tot.y += acc.y * inv;
        tot.z += acc.z * inv; tot.w += acc.w * inv;
    }
    tot.x = fmaxf(tot.x, 0.f); tot.y = fmaxf(tot.y, 0.f);
    tot.z = fmaxf(tot.z, 0.f); tot.w = fmaxf(tot.w, 0.f);
    ((float4*)(out + (size_t)gw * DD))[lane] = tot;
}

// ---------------------------------------------------------------------------
extern "C" void kernel_launch(void* const* d_in, const int* in_sizes, int n_in,
                              void* d_out, int out_size) {
    const float* x = (const float*)d_in[0];      // [100000,128]
    const float* W = (const float*)d_in[1];      // [4,128,128]
    const float* b = (const float*)d_in[2];      // [4,128]
    const int* src_idx = (const int*)d_in[3];    // [4,500000]
    const int* dst_idx = (const int*)d_in[4];    // [4,500000]
    float* out = (float*)d_out;                  // [100000,128]

    cudaFuncSetAttribute(k_gemm_mma, cudaFuncAttributeMaxDynamicSharedMemorySize,
                         SMEM_MMA);

    // Build padded bucket-CSR (counts double as degrees).
    k_zero_cnt<<<(NR * NN + 255) / 256, 256>>>();
    k_fill<<<(NR * NE + 255) / 256, 256>>>(src_idx, dst_idx);

    // z[r] = x @ W[r] via HMMA split-fp16, z stored fp16.
    int mtiles = (NN + 127) / 128;               // 782
    k_gemm_mma<<<mtiles, 256, SMEM_MMA>>>(x, W);

    // Fused gather + bias + ReLU (handles overflow inline; writes every row).
    k_scatter_f<<<(NN + 7) / 8, 256>>>(src_idx, dst_idx, b, out);
}